// round 10
// baseline (speedup 1.0000x reference)
#include <cuda_runtime.h>
#include <cstdint>

// CensusLoss: 5x5 census hamming, reflect pad, mean. (8,3,512,512) fp32 in [0,1).
// Total = 2 * sum_x sum_{d in D12} f(x, R(x+d)) + C (boundary strip correction).
// Persistent blocks, cp.async double-buffered halo pipeline.

#define HH   512
#define WW   512
#define TW   128
#define TH   8
#define SW   (TW + 4)      // 132
#define SH   (TH + 2)      // 10
#define NELEM 6291456.0
#define NTILES 6144        // 4 x 64 x 24
#define NBLK   740         // 5 blocks/SM x 148 SMs
#define STRIP  4080
#define CORR_FIRST (NBLK - 72)

__device__ unsigned g_acc = 0;
__device__ unsigned g_cnt = 0;

__device__ __forceinline__ int refl(int i, int n) {
    i = (i < 0) ? -i : i;
    return (i >= n) ? (2 * n - 2 - i) : i;
}

// (a<b) ^ (c<d) for positive floats via sign bits (tie-exact: a==b -> +0 -> 0)
__device__ __forceinline__ unsigned sb2(float a, float b, float c, float d) {
    return (unsigned)(__float_as_int(a - b) ^ __float_as_int(c - d)) >> 31;
}

__device__ __forceinline__ void cpa4(uint32_t dst, const float* src) {
    asm volatile("cp.async.ca.shared.global [%0], [%1], 4;" :: "r"(dst), "l"(src));
}

__device__ __forceinline__ void prefetch_tile(int t, float (*sp)[SW], float (*sg)[SW],
                                              const float* __restrict__ pred,
                                              const float* __restrict__ gt, int tid)
{
    const int img  = t >> 8;
    const int tl   = t & 255;
    const int row0 = (tl >> 2) * TH;
    const int col0 = (tl & 3) * TW;
    const float* p = pred + (size_t)img * HH * WW;
    const float* g = gt   + (size_t)img * HH * WW;
    #pragma unroll
    for (int k = 0; k < 6; ++k) {
        int idx = tid + k * 256;
        if (idx < SH * SW) {
            int lr = idx / SW;
            int lc = idx - lr * SW;
            int r = row0 + lr; r = (r >= HH) ? (2 * HH - 2 - r) : r;   // bottom reflect only
            int c = refl(col0 + lc - 2, WW);
            int off = r * WW + c;
            cpa4((uint32_t)__cvta_generic_to_shared(&sp[lr][lc]), p + off);
            cpa4((uint32_t)__cvta_generic_to_shared(&sg[lr][lc]), g + off);
        }
    }
}

__device__ __forceinline__ void compute_tile(const float (*sp)[SW], const float (*sg)[SW],
                                             int tid, unsigned& a0, unsigned& a1,
                                             unsigned& a2, unsigned& a3)
{
    const int ty = tid >> 5;          // warp = output row
    const int bx = (tid & 31) * 4;    // 4-px micro-tile

    float P[8], G[8], Q[8], H[8];
    ((float4*)P)[0] = *(const float4*)&sp[ty][bx]; ((float4*)P)[1] = *(const float4*)&sp[ty][bx + 4];
    ((float4*)G)[0] = *(const float4*)&sg[ty][bx]; ((float4*)G)[1] = *(const float4*)&sg[ty][bx + 4];

    // dr=0: centers P[k+2]; offsets (0,1),(0,2)
    #pragma unroll
    for (int k = 0; k < 4; ++k) {
        a0 += sb2(P[k + 3], P[k + 2], G[k + 3], G[k + 2]);
        a1 += sb2(P[k + 4], P[k + 2], G[k + 4], G[k + 2]);
    }
    // dr=1,2: dc=-2..2
    #pragma unroll
    for (int dr = 1; dr <= 2; ++dr) {
        ((float4*)Q)[0] = *(const float4*)&sp[ty + dr][bx]; ((float4*)Q)[1] = *(const float4*)&sp[ty + dr][bx + 4];
        ((float4*)H)[0] = *(const float4*)&sg[ty + dr][bx]; ((float4*)H)[1] = *(const float4*)&sg[ty + dr][bx + 4];
        #pragma unroll
        for (int k = 0; k < 4; ++k) {
            a0 += sb2(Q[k + 0], P[k + 2], H[k + 0], G[k + 2]);
            a1 += sb2(Q[k + 1], P[k + 2], H[k + 1], G[k + 2]);
            a2 += sb2(Q[k + 2], P[k + 2], H[k + 2], G[k + 2]);
            a3 += sb2(Q[k + 3], P[k + 2], H[k + 3], G[k + 2]);
            a0 += sb2(Q[k + 4], P[k + 2], H[k + 4], G[k + 2]);
        }
    }
}

__global__ __launch_bounds__(256, 5)
void census_kernel(const float* __restrict__ pred, const float* __restrict__ gt,
                   float* __restrict__ out)
{
    __shared__ __align__(16) float sb[2][2][SH][SW];   // [buf][p/g][row][col]
    __shared__ int wsum[8];

    const int tid = threadIdx.x;
    const int bid = blockIdx.x;

    unsigned a0 = 0, a1 = 0, a2 = 0, a3 = 0;

    const int nt = (NTILES - 1 - bid) / NBLK + 1;   // 8 or 9 tiles per block

    prefetch_tile(bid, sb[0][0], sb[0][1], pred, gt, tid);
    asm volatile("cp.async.commit_group;");

    for (int i = 0; i < nt; ++i) {
        const bool more = (i + 1 < nt);
        if (more) {
            prefetch_tile(bid + (i + 1) * NBLK, sb[(i + 1) & 1][0], sb[(i + 1) & 1][1],
                          pred, gt, tid);
            asm volatile("cp.async.commit_group;");
            asm volatile("cp.async.wait_group 1;");
        } else {
            asm volatile("cp.async.wait_group 0;");
        }
        __syncthreads();
        compute_tile(sb[i & 1][0], sb[i & 1][1], tid, a0, a1, a2, a3);
        __syncthreads();   // buffer i&1 safe to overwrite next iteration
    }

    int contrib = (int)(2u * (a0 + a1 + a2 + a3));

    // -------- boundary correction strip (last 72 blocks) --------
    if (bid >= CORR_FIRST) {
        const int DR[12] = {0, 0, 1, 1, 1, 1, 1, 2, 2, 2, 2, 2};
        const int DC[12] = {1, 2,-2,-1, 0, 1, 2,-2,-1, 0, 1, 2};
        for (int imgc = 0; imgc < 24; ++imgc) {
            const float* p = pred + (size_t)imgc * HH * WW;
            const float* g = gt   + (size_t)imgc * HH * WW;
            for (int s = (bid - CORR_FIRST) * 256 + tid; s < STRIP; s += 72 * 256) {
                int r, c;
                if (s < 2048) {
                    int ri = s >> 9;
                    r = (ri < 2) ? ri : (508 + ri);
                    c = s & 511;
                } else {
                    int t2 = s - 2048;
                    int ci = t2 & 3;
                    c = (ci < 2) ? ci : (508 + ci);
                    r = 2 + (t2 >> 2);
                }
                const float pcv = p[r * WW + c];
                const float gcv = g[r * WW + c];
                #pragma unroll
                for (int o = 0; o < 12; ++o) {
                    const int dr = DR[o], dc = DC[o];
                    int rm = r - dr, cm = c - dc;
                    if ((unsigned)rm >= HH || (unsigned)cm >= WW) {
                        int rr = refl(rm, HH) * WW + refl(cm, WW);
                        contrib += (int)sb2(p[rr], pcv, g[rr], gcv);
                    }
                    int rp = r + dr, cp = c + dc;
                    if ((unsigned)rp >= HH || (unsigned)cp >= WW) {
                        int rr = refl(rp, HH) * WW + refl(cp, WW);
                        contrib -= (int)sb2(p[rr], pcv, g[rr], gcv);
                    }
                }
            }
        }
    }

    // -------- exact integer reduction + last-block finalize --------
    contrib = __reduce_add_sync(0xffffffffu, contrib);
    if ((tid & 31) == 0) wsum[tid >> 5] = contrib;
    __syncthreads();

    if (tid == 0) {
        int s = 0;
        #pragma unroll
        for (int w = 0; w < 8; ++w) s += wsum[w];
        atomicAdd(&g_acc, (unsigned)s);
        __threadfence();
        unsigned t = atomicAdd(&g_cnt, 1u);
        if (t == NBLK - 1) {
            __threadfence();
            unsigned total = atomicExch(&g_acc, 0u);   // read + reset for next replay
            out[0] = (float)((double)total / NELEM);
            g_cnt = 0;
        }
    }
}

extern "C" void kernel_launch(void* const* d_in, const int* in_sizes, int n_in,
                              void* d_out, int out_size)
{
    const float* pred = (const float*)d_in[0];
    const float* gt   = (const float*)d_in[1];
    float* out        = (float*)d_out;

    census_kernel<<<NBLK, 256>>>(pred, gt, out);
}

// round 13
// speedup vs baseline: 1.9426x; 1.9426x over previous
#include <cuda_runtime.h>
#include <cstdint>

// CensusLoss: 5x5 census hamming, reflect pad, mean. (8,3,512,512) fp32 in [0,1).
// Total = 2 * sum_x sum_{d in D12} f(x, R(x+d)) + C (boundary strip correction).
// Packed f32x2 compare core on p/g-interleaved, XOR-swizzled smem rows.

typedef unsigned long long ull;

#define HH   512
#define WW   512
#define NIMG 24
#define TW   128
#define TH   8
#define NCOL 132               // halo cols col0-2 .. col0+129
#define ROWB 2048              // padded row stride in bytes
#define NELEM 6291456.0
#define MAIN_BLOCKS ((WW/TW)*(HH/TH)*NIMG)   // 6144
#define TOTAL_BLOCKS (MAIN_BLOCKS + 4*NIMG)  // + 96 strip blocks
#define STRIP 4080

__device__ unsigned g_acc = 0;
__device__ unsigned g_cnt = 0;

__device__ __forceinline__ int refl(int i, int n) {
    i = (i < 0) ? -i : i;
    return (i >= n) ? (2 * n - 2 - i) : i;
}

// swizzle for 8B-aligned in-row byte offsets (XOR bits [6:4] with bits [9:7])
__device__ __forceinline__ int sw8(int o) { return o ^ ((o >> 3) & 0x70); }

__device__ __forceinline__ ull addx2(ull a, ull b) {
    ull d; asm("add.rn.f32x2 %0, %1, %2;" : "=l"(d) : "l"(a), "l"(b)); return d;
}
__device__ __forceinline__ ull negx2(ull a) {
    ull d; asm("mul.rn.f32x2 %0, %1, %2;" : "=l"(d) : "l"(a), "l"(0xBF800000BF800000ULL));
    return d;
}
// sign(lo) ^ sign(hi) of packed diffs (caller shifts >>31)
__device__ __forceinline__ unsigned xsign(ull d) {
    return (unsigned)(d >> 32) ^ (unsigned)d;
}
// scalar fallback (strip path): (a<b)^(c<d) for positive floats
__device__ __forceinline__ unsigned sb2(float a, float b, float c, float d) {
    return (unsigned)(__float_as_int(a - b) ^ __float_as_int(c - d)) >> 31;
}

__global__ __launch_bounds__(256, 6)
void census_kernel(const float* __restrict__ pred, const float* __restrict__ gt,
                   float* __restrict__ out)
{
    __shared__ __align__(16) char smem[10 * ROWB];   // 10 rows x (132+pad) float2 (p,g)
    __shared__ int wsum[8];

    const int tid = threadIdx.x;
    const int img = blockIdx.z;
    const float* __restrict__ p = pred + (size_t)img * HH * WW;
    const float* __restrict__ g = gt   + (size_t)img * HH * WW;

    int contrib = 0;

    if (blockIdx.y < HH / TH) {
        const int row0 = blockIdx.y * TH;
        const int col0 = blockIdx.x * TW;

        // ---------------- halo load (interleaved + swizzled) ----------------
        const bool interior = (blockIdx.x > 0) && (blockIdx.x < 3) && (blockIdx.y < 63);
        if (interior) {
            // 660 two-col granules, float2 gmem loads (col0-2 is even -> 8B aligned)
            for (int idx = tid; idx < 660; idx += 256) {
                int lr = idx / 66;
                int l2 = idx - lr * 66;
                const float* rp = p + (row0 + lr) * WW + (col0 - 2) + 2 * l2;
                const float* rg = g + (row0 + lr) * WW + (col0 - 2) + 2 * l2;
                float2 pv = *(const float2*)rp;
                float2 gv = *(const float2*)rg;
                char* d = smem + lr * ROWB + sw8(l2 * 16);
                *(float2*)(d)     = make_float2(pv.x, gv.x);
                *(float2*)(d + 8) = make_float2(pv.y, gv.y);
            }
        } else {
            for (int idx = tid; idx < 10 * NCOL; idx += 256) {
                int lr = idx / NCOL;
                int lc = idx - lr * NCOL;
                int r = row0 + lr; r = (r >= HH) ? (2 * HH - 2 - r) : r;
                int c = refl(col0 + lc - 2, WW);
                *(float2*)(smem + lr * ROWB + sw8(lc * 8)) =
                    make_float2(p[r * WW + c], g[r * WW + c]);
            }
        }
        __syncthreads();

        // ------- packed halved census: warp = row, thread = 4 px (cols lane*4..+7) -------
        const int ty   = tid >> 5;
        const int lane = tid & 31;
        const int lb   = lane * 32;                 // byte base: float2 index lane*4
        const int b0 = sw8(lb +  0), b1 = sw8(lb + 16),
                  b2 = sw8(lb + 32), b3 = sw8(lb + 48);   // per-access swizzle (carry!)
        const char* rbase = smem + ty * ROWB;

        unsigned a0 = 0, a1 = 0, a2 = 0, a3 = 0;
        ull nc0, nc1, nc2, nc3;

        {   // row dr=0: centers + offsets (0,1),(0,2)
            ulonglong2 c0 = *(const ulonglong2*)(rbase + b0);   // cols j=0,1
            ulonglong2 c1 = *(const ulonglong2*)(rbase + b1);   // cols j=2,3
            ulonglong2 c2 = *(const ulonglong2*)(rbase + b2);   // cols j=4,5
            ulonglong2 c3 = *(const ulonglong2*)(rbase + b3);   // cols j=6,7
            (void)c0;
            nc0 = negx2(c1.x);   // center k=0 at j=2
            nc1 = negx2(c1.y);   // k=1 at j=3
            nc2 = negx2(c2.x);   // k=2 at j=4
            nc3 = negx2(c2.y);   // k=3 at j=5
            // dc=1: j=k+3 ; dc=2: j=k+4
            a0 += xsign(addx2(c1.y, nc0)) >> 31;  a0 += xsign(addx2(c2.x, nc0)) >> 31;
            a1 += xsign(addx2(c2.x, nc1)) >> 31;  a1 += xsign(addx2(c2.y, nc1)) >> 31;
            a2 += xsign(addx2(c2.y, nc2)) >> 31;  a2 += xsign(addx2(c3.x, nc2)) >> 31;
            a3 += xsign(addx2(c3.x, nc3)) >> 31;  a3 += xsign(addx2(c3.y, nc3)) >> 31;
        }

        #pragma unroll
        for (int dr = 1; dr <= 2; ++dr) {
            const char* rp = rbase + dr * ROWB;
            ulonglong2 c0 = *(const ulonglong2*)(rp + b0);
            ulonglong2 c1 = *(const ulonglong2*)(rp + b1);
            ulonglong2 c2 = *(const ulonglong2*)(rp + b2);
            ulonglong2 c3 = *(const ulonglong2*)(rp + b3);
            ull pg[8] = {c0.x, c0.y, c1.x, c1.y, c2.x, c2.y, c3.x, c3.y};
            // dc = -2..2 : neighbor j = k + dc + 2
            #pragma unroll
            for (int dc = -2; dc <= 2; ++dc) {
                a0 += xsign(addx2(pg[0 + dc + 2], nc0)) >> 31;
                a1 += xsign(addx2(pg[1 + dc + 2], nc1)) >> 31;
                a2 += xsign(addx2(pg[2 + dc + 2], nc2)) >> 31;
                a3 += xsign(addx2(pg[3 + dc + 2], nc3)) >> 31;
            }
        }
        contrib = (int)(2u * (a0 + a1 + a2 + a3));
    } else {
        // ---------------- boundary correction strip ----------------
        const int DR[12] = {0, 0, 1, 1, 1, 1, 1, 2, 2, 2, 2, 2};
        const int DC[12] = {1, 2,-2,-1, 0, 1, 2,-2,-1, 0, 1, 2};
        for (int s = blockIdx.x * 256 + tid; s < STRIP; s += 1024) {
            int r, c;
            if (s < 2048) {
                int ri = s >> 9;
                r = (ri < 2) ? ri : (508 + ri);
                c = s & 511;
            } else {
                int t2 = s - 2048;
                int ci = t2 & 3;
                c = (ci < 2) ? ci : (508 + ci);
                r = 2 + (t2 >> 2);
            }
            const float pcv = p[r * WW + c];
            const float gcv = g[r * WW + c];
            #pragma unroll
            for (int o = 0; o < 12; ++o) {
                const int dr = DR[o], dc = DC[o];
                int rm = r - dr, cm = c - dc;
                if ((unsigned)rm >= HH || (unsigned)cm >= WW) {
                    int rr = refl(rm, HH) * WW + refl(cm, WW);
                    contrib += (int)sb2(p[rr], pcv, g[rr], gcv);
                }
                int rp2 = r + dr, cp = c + dc;
                if ((unsigned)rp2 >= HH || (unsigned)cp >= WW) {
                    int rr = refl(rp2, HH) * WW + refl(cp, WW);
                    contrib -= (int)sb2(p[rr], pcv, g[rr], gcv);
                }
            }
        }
    }

    // ---------------- exact integer reduction + last-block finalize ----------------
    contrib = __reduce_add_sync(0xffffffffu, contrib);
    if ((tid & 31) == 0) wsum[tid >> 5] = contrib;
    __syncthreads();

    if (tid == 0) {
        int s = 0;
        #pragma unroll
        for (int w = 0; w < 8; ++w) s += wsum[w];
        atomicAdd(&g_acc, (unsigned)s);
        __threadfence();
        unsigned t = atomicAdd(&g_cnt, 1u);
        if (t == TOTAL_BLOCKS - 1) {
            __threadfence();
            unsigned total = atomicExch(&g_acc, 0u);   // read + reset for next replay
            out[0] = (float)((double)total / NELEM);
            g_cnt = 0;
        }
    }
}

extern "C" void kernel_launch(void* const* d_in, const int* in_sizes, int n_in,
                              void* d_out, int out_size)
{
    const float* pred = (const float*)d_in[0];
    const float* gt   = (const float*)d_in[1];
    float* out        = (float*)d_out;

    dim3 grid(WW / TW, HH / TH + 1, NIMG);   // (4, 65, 24): y==64 -> strip blocks
    census_kernel<<<grid, 256>>>(pred, gt, out);
}

// round 14
// speedup vs baseline: 2.1377x; 1.1004x over previous
#include <cuda_runtime.h>
#include <cstdint>

// CensusLoss: 5x5 census hamming, reflect pad, mean. (8,3,512,512) fp32 in [0,1).
// Total = 2 * sum_x sum_{d in D12} f(x, R(x+d)) + C (boundary strip correction).
// Packed f32x2 core, p/g-interleaved swizzled smem, vertical register rolling
// (thread = 4 px wide x 4 center rows; one fresh row-load per center row).

typedef unsigned long long ull;

#define HH   512
#define WW   512
#define NIMG 24
#define TW   128
#define TH2  32                // tile height (4 center rows per warp x 8 warps)
#define NROW 34                // smem rows: TH2 + 2 halo below
#define NCOL 132               // halo cols col0-2 .. col0+129
#define ROWB 1152              // row stride bytes (132*8=1056 padded; multiple of 128)
#define NELEM 6291456.0
#define MAIN_BLOCKS ((WW/TW)*(HH/TH2)*NIMG)    // 4*16*24 = 1536
#define TOTAL_BLOCKS (MAIN_BLOCKS + 4*NIMG)    // + 96 strip blocks
#define STRIP 4080

__device__ unsigned g_acc = 0;
__device__ unsigned g_cnt = 0;

__device__ __forceinline__ int refl(int i, int n) {
    i = (i < 0) ? -i : i;
    return (i >= n) ? (2 * n - 2 - i) : i;
}
// swizzle for 8B-aligned in-row byte offsets (XOR bits [6:4] with [9:7]) — stays in-line
__device__ __forceinline__ int sw8(int o) { return o ^ ((o >> 3) & 0x70); }

__device__ __forceinline__ ull addx2(ull a, ull b) {
    ull d; asm("add.rn.f32x2 %0, %1, %2;" : "=l"(d) : "l"(a), "l"(b)); return d;
}
__device__ __forceinline__ ull negx2(ull a) {
    ull d; asm("mul.rn.f32x2 %0, %1, %2;" : "=l"(d) : "l"(a), "l"(0xBF800000BF800000ULL));
    return d;
}
__device__ __forceinline__ unsigned xs(ull d) {           // sign(lo)^sign(hi) at bit31
    return (unsigned)(d >> 32) ^ (unsigned)d;
}
__device__ __forceinline__ unsigned sb2(float a, float b, float c, float d) {
    return (unsigned)(__float_as_int(a - b) ^ __float_as_int(c - d)) >> 31;
}

__global__ __launch_bounds__(256, 5)
void census_kernel(const float* __restrict__ pred, const float* __restrict__ gt,
                   float* __restrict__ out)
{
    __shared__ __align__(16) char smem[NROW * ROWB];   // interleaved (p,g) float2, swizzled
    __shared__ int wsum[8];

    const int tid = threadIdx.x;
    const int img = blockIdx.z;
    const float* __restrict__ p = pred + (size_t)img * HH * WW;
    const float* __restrict__ g = gt   + (size_t)img * HH * WW;

    int contrib = 0;

    if (blockIdx.y < HH / TH2) {
        const int row0 = blockIdx.y * TH2;
        const int col0 = blockIdx.x * TW;

        // ---------------- halo load (interleaved + swizzled) ----------------
        const bool interior = (blockIdx.x > 0) && (blockIdx.x < 3) &&
                              (blockIdx.y < HH / TH2 - 1);
        if (interior) {
            for (int idx = tid; idx < NROW * 66; idx += 256) {
                int lr = idx / 66;
                int l2 = idx - lr * 66;
                const float* rp = p + (row0 + lr) * WW + (col0 - 2) + 2 * l2;
                const float* rg = g + (row0 + lr) * WW + (col0 - 2) + 2 * l2;
                float2 pv = *(const float2*)rp;
                float2 gv = *(const float2*)rg;
                char* d = smem + lr * ROWB + sw8(l2 * 16);
                *(float2*)(d)     = make_float2(pv.x, gv.x);
                *(float2*)(d + 8) = make_float2(pv.y, gv.y);
            }
        } else {
            for (int idx = tid; idx < NROW * NCOL; idx += 256) {
                int lr = idx / NCOL;
                int lc = idx - lr * NCOL;
                int r = refl(row0 + lr, HH);              // bottom reflect only in practice
                int c = refl(col0 + lc - 2, WW);
                *(float2*)(smem + lr * ROWB + sw8(lc * 8)) =
                    make_float2(p[r * WW + c], g[r * WW + c]);
            }
        }
        __syncthreads();

        // ------- rolling census: warp = 128 cols x 4 center rows, thread = 4 px -------
        const int ty0  = (tid >> 5) * 4;            // first center row (smem row index)
        const int lane = tid & 31;
        const int lb   = lane * 32;                 // byte base: float2 col index lane*4
        const int b0 = sw8(lb +  0), b1 = sw8(lb + 16),
                  b2 = sw8(lb + 32), b3 = sw8(lb + 48);

        unsigned a0 = 0, a1 = 0, a2 = 0, a3 = 0;
        ull A[8], B[8], C[8], nc0, nc1, nc2, nc3;

#define LDROW(r, R) { const char* rp_ = smem + (r) * ROWB;              \
        ulonglong2 u0 = *(const ulonglong2*)(rp_ + b0);                 \
        ulonglong2 u1 = *(const ulonglong2*)(rp_ + b1);                 \
        ulonglong2 u2 = *(const ulonglong2*)(rp_ + b2);                 \
        ulonglong2 u3 = *(const ulonglong2*)(rp_ + b3);                 \
        R[0]=u0.x; R[1]=u0.y; R[2]=u1.x; R[3]=u1.y;                     \
        R[4]=u2.x; R[5]=u2.y; R[6]=u3.x; R[7]=u3.y; }

        // centers at cols j=2..5 of window; dr0 offsets (0,1),(0,2): j=k+3, k+4
#define CENTERS_DR0(T) {                                                \
        nc0 = negx2(T[2]); nc1 = negx2(T[3]);                           \
        nc2 = negx2(T[4]); nc3 = negx2(T[5]);                           \
        a0 += xs(addx2(T[3], nc0)) >> 31;  a0 += xs(addx2(T[4], nc0)) >> 31; \
        a1 += xs(addx2(T[4], nc1)) >> 31;  a1 += xs(addx2(T[5], nc1)) >> 31; \
        a2 += xs(addx2(T[5], nc2)) >> 31;  a2 += xs(addx2(T[6], nc2)) >> 31; \
        a3 += xs(addx2(T[6], nc3)) >> 31;  a3 += xs(addx2(T[7], nc3)) >> 31; }

        // full row vs centers: dc=-2..2 -> j = k + dc + 2
#define CMPROW(Y) {                                                     \
        _Pragma("unroll")                                               \
        for (int dc = 0; dc < 5; ++dc) {                                \
            a0 += xs(addx2(Y[dc + 0], nc0)) >> 31;                      \
            a1 += xs(addx2(Y[dc + 1], nc1)) >> 31;                      \
            a2 += xs(addx2(Y[dc + 2], nc2)) >> 31;                      \
            a3 += xs(addx2(Y[dc + 3], nc3)) >> 31;                      \
        } }

        LDROW(ty0 + 0, A); LDROW(ty0 + 1, B);
        CENTERS_DR0(A); CMPROW(B); LDROW(ty0 + 2, C); CMPROW(C);
        CENTERS_DR0(B); CMPROW(C); LDROW(ty0 + 3, A); CMPROW(A);
        CENTERS_DR0(C); CMPROW(A); LDROW(ty0 + 4, B); CMPROW(B);
        CENTERS_DR0(A); CMPROW(B); LDROW(ty0 + 5, C); CMPROW(C);

        contrib = (int)(2u * (a0 + a1 + a2 + a3));
#undef LDROW
#undef CENTERS_DR0
#undef CMPROW
    } else {
        // ---------------- boundary correction strip ----------------
        const int DR[12] = {0, 0, 1, 1, 1, 1, 1, 2, 2, 2, 2, 2};
        const int DC[12] = {1, 2,-2,-1, 0, 1, 2,-2,-1, 0, 1, 2};
        for (int s = blockIdx.x * 256 + tid; s < STRIP; s += 1024) {
            int r, c;
            if (s < 2048) {
                int ri = s >> 9;
                r = (ri < 2) ? ri : (508 + ri);
                c = s & 511;
            } else {
                int t2 = s - 2048;
                int ci = t2 & 3;
                c = (ci < 2) ? ci : (508 + ci);
                r = 2 + (t2 >> 2);
            }
            const float pcv = p[r * WW + c];
            const float gcv = g[r * WW + c];
            #pragma unroll
            for (int o = 0; o < 12; ++o) {
                const int dr = DR[o], dc = DC[o];
                int rm = r - dr, cm = c - dc;
                if ((unsigned)rm >= HH || (unsigned)cm >= WW) {
                    int rr = refl(rm, HH) * WW + refl(cm, WW);
                    contrib += (int)sb2(p[rr], pcv, g[rr], gcv);
                }
                int rp2 = r + dr, cp = c + dc;
                if ((unsigned)rp2 >= HH || (unsigned)cp >= WW) {
                    int rr = refl(rp2, HH) * WW + refl(cp, WW);
                    contrib -= (int)sb2(p[rr], pcv, g[rr], gcv);
                }
            }
        }
    }

    // ---------------- exact integer reduction + last-block finalize ----------------
    contrib = __reduce_add_sync(0xffffffffu, contrib);
    if ((tid & 31) == 0) wsum[tid >> 5] = contrib;
    __syncthreads();

    if (tid == 0) {
        int s = 0;
        #pragma unroll
        for (int w = 0; w < 8; ++w) s += wsum[w];
        atomicAdd(&g_acc, (unsigned)s);
        __threadfence();
        unsigned t = atomicAdd(&g_cnt, 1u);
        if (t == TOTAL_BLOCKS - 1) {
            __threadfence();
            unsigned total = atomicExch(&g_acc, 0u);   // read + reset for next replay
            out[0] = (float)((double)total / NELEM);
            g_cnt = 0;
        }
    }
}

extern "C" void kernel_launch(void* const* d_in, const int* in_sizes, int n_in,
                              void* d_out, int out_size)
{
    const float* pred = (const float*)d_in[0];
    const float* gt   = (const float*)d_in[1];
    float* out        = (float*)d_out;

    dim3 grid(WW / TW, HH / TH2 + 1, NIMG);   // (4, 17, 24): y==16 -> strip blocks
    census_kernel<<<grid, 256>>>(pred, gt, out);
}

// round 15
// speedup vs baseline: 2.2384x; 1.0471x over previous
#include <cuda_runtime.h>
#include <cstdint>

// CensusLoss: 5x5 census hamming, reflect pad, mean. (8,3,512,512) fp32 in [0,1).
// Total = 2 * sum_x sum_{d in D12} f(x, R(x+d)) + C (boundary strip correction).
// Packed f32x2 core, p/g-interleaved swizzled smem, vertical register rolling.
// This round: ROWB 1152->1088 + launch_bounds(256,6) => 6 blocks/SM, 2 clean waves.

typedef unsigned long long ull;

#define HH   512
#define WW   512
#define NIMG 24
#define TW   128
#define TH2  32                // tile height (4 center rows per warp x 8 warps)
#define NROW 34                // smem rows: TH2 + 2 halo below
#define NCOL 132               // halo cols col0-2 .. col0+129
#define ROWB 1088              // row stride bytes (132*8=1056, padded to 16B multiple)
#define NELEM 6291456.0
#define MAIN_BLOCKS ((WW/TW)*(HH/TH2)*NIMG)    // 4*16*24 = 1536
#define TOTAL_BLOCKS (MAIN_BLOCKS + 4*NIMG)    // + 96 strip blocks
#define STRIP 4080

__device__ unsigned g_acc = 0;
__device__ unsigned g_cnt = 0;

__device__ __forceinline__ int refl(int i, int n) {
    i = (i < 0) ? -i : i;
    return (i >= n) ? (2 * n - 2 - i) : i;
}
// swizzle for 8B-aligned in-row byte offsets (XOR bits [6:4] with [9:7])
__device__ __forceinline__ int sw8(int o) { return o ^ ((o >> 3) & 0x70); }

__device__ __forceinline__ ull addx2(ull a, ull b) {
    ull d; asm("add.rn.f32x2 %0, %1, %2;" : "=l"(d) : "l"(a), "l"(b)); return d;
}
__device__ __forceinline__ ull negx2(ull a) {
    ull d; asm("mul.rn.f32x2 %0, %1, %2;" : "=l"(d) : "l"(a), "l"(0xBF800000BF800000ULL));
    return d;
}
__device__ __forceinline__ unsigned xs(ull d) {           // sign(lo)^sign(hi) at bit31
    return (unsigned)(d >> 32) ^ (unsigned)d;
}
__device__ __forceinline__ unsigned sb2(float a, float b, float c, float d) {
    return (unsigned)(__float_as_int(a - b) ^ __float_as_int(c - d)) >> 31;
}

__global__ __launch_bounds__(256, 6)
void census_kernel(const float* __restrict__ pred, const float* __restrict__ gt,
                   float* __restrict__ out)
{
    __shared__ __align__(16) char smem[NROW * ROWB];   // interleaved (p,g) float2, swizzled
    __shared__ int wsum[8];

    const int tid = threadIdx.x;
    const int img = blockIdx.z;
    const float* __restrict__ p = pred + (size_t)img * HH * WW;
    const float* __restrict__ g = gt   + (size_t)img * HH * WW;

    int contrib = 0;

    if (blockIdx.y < HH / TH2) {
        const int row0 = blockIdx.y * TH2;
        const int col0 = blockIdx.x * TW;

        // ---------------- halo load (interleaved + swizzled) ----------------
        const bool interior = (blockIdx.x > 0) && (blockIdx.x < 3) &&
                              (blockIdx.y < HH / TH2 - 1);
        if (interior) {
            for (int idx = tid; idx < NROW * 66; idx += 256) {
                int lr = idx / 66;
                int l2 = idx - lr * 66;
                const float* rp = p + (row0 + lr) * WW + (col0 - 2) + 2 * l2;
                const float* rg = g + (row0 + lr) * WW + (col0 - 2) + 2 * l2;
                float2 pv = *(const float2*)rp;
                float2 gv = *(const float2*)rg;
                char* d = smem + lr * ROWB + sw8(l2 * 16);
                *(float2*)(d)     = make_float2(pv.x, gv.x);
                *(float2*)(d + 8) = make_float2(pv.y, gv.y);
            }
        } else {
            for (int idx = tid; idx < NROW * NCOL; idx += 256) {
                int lr = idx / NCOL;
                int lc = idx - lr * NCOL;
                int r = refl(row0 + lr, HH);
                int c = refl(col0 + lc - 2, WW);
                *(float2*)(smem + lr * ROWB + sw8(lc * 8)) =
                    make_float2(p[r * WW + c], g[r * WW + c]);
            }
        }
        __syncthreads();

        // ------- rolling census: warp = 128 cols x 4 center rows, thread = 4 px -------
        const int ty0  = (tid >> 5) * 4;            // first center row (smem row index)
        const int lane = tid & 31;
        const int lb   = lane * 32;                 // byte base: float2 col index lane*4
        const int b0 = sw8(lb +  0), b1 = sw8(lb + 16),
                  b2 = sw8(lb + 32), b3 = sw8(lb + 48);

        unsigned a0 = 0, a1 = 0, a2 = 0, a3 = 0;
        ull A[8], B[8], C[8], nc0, nc1, nc2, nc3;

#define LDROW(r, R) { const char* rp_ = smem + (r) * ROWB;              \
        ulonglong2 u0 = *(const ulonglong2*)(rp_ + b0);                 \
        ulonglong2 u1 = *(const ulonglong2*)(rp_ + b1);                 \
        ulonglong2 u2 = *(const ulonglong2*)(rp_ + b2);                 \
        ulonglong2 u3 = *(const ulonglong2*)(rp_ + b3);                 \
        R[0]=u0.x; R[1]=u0.y; R[2]=u1.x; R[3]=u1.y;                     \
        R[4]=u2.x; R[5]=u2.y; R[6]=u3.x; R[7]=u3.y; }

#define CENTERS_DR0(T) {                                                \
        nc0 = negx2(T[2]); nc1 = negx2(T[3]);                           \
        nc2 = negx2(T[4]); nc3 = negx2(T[5]);                           \
        a0 += xs(addx2(T[3], nc0)) >> 31;  a0 += xs(addx2(T[4], nc0)) >> 31; \
        a1 += xs(addx2(T[4], nc1)) >> 31;  a1 += xs(addx2(T[5], nc1)) >> 31; \
        a2 += xs(addx2(T[5], nc2)) >> 31;  a2 += xs(addx2(T[6], nc2)) >> 31; \
        a3 += xs(addx2(T[6], nc3)) >> 31;  a3 += xs(addx2(T[7], nc3)) >> 31; }

#define CMPROW(Y) {                                                     \
        _Pragma("unroll")                                               \
        for (int dc = 0; dc < 5; ++dc) {                                \
            a0 += xs(addx2(Y[dc + 0], nc0)) >> 31;                      \
            a1 += xs(addx2(Y[dc + 1], nc1)) >> 31;                      \
            a2 += xs(addx2(Y[dc + 2], nc2)) >> 31;                      \
            a3 += xs(addx2(Y[dc + 3], nc3)) >> 31;                      \
        } }

        LDROW(ty0 + 0, A); LDROW(ty0 + 1, B);
        CENTERS_DR0(A); CMPROW(B); LDROW(ty0 + 2, C); CMPROW(C);
        CENTERS_DR0(B); CMPROW(C); LDROW(ty0 + 3, A); CMPROW(A);
        CENTERS_DR0(C); CMPROW(A); LDROW(ty0 + 4, B); CMPROW(B);
        CENTERS_DR0(A); CMPROW(B); LDROW(ty0 + 5, C); CMPROW(C);

        contrib = (int)(2u * (a0 + a1 + a2 + a3));
#undef LDROW
#undef CENTERS_DR0
#undef CMPROW
    } else {
        // ---------------- boundary correction strip ----------------
        const int DR[12] = {0, 0, 1, 1, 1, 1, 1, 2, 2, 2, 2, 2};
        const int DC[12] = {1, 2,-2,-1, 0, 1, 2,-2,-1, 0, 1, 2};
        for (int s = blockIdx.x * 256 + tid; s < STRIP; s += 1024) {
            int r, c;
            if (s < 2048) {
                int ri = s >> 9;
                r = (ri < 2) ? ri : (508 + ri);
                c = s & 511;
            } else {
                int t2 = s - 2048;
                int ci = t2 & 3;
                c = (ci < 2) ? ci : (508 + ci);
                r = 2 + (t2 >> 2);
            }
            const float pcv = p[r * WW + c];
            const float gcv = g[r * WW + c];
            #pragma unroll
            for (int o = 0; o < 12; ++o) {
                const int dr = DR[o], dc = DC[o];
                int rm = r - dr, cm = c - dc;
                if ((unsigned)rm >= HH || (unsigned)cm >= WW) {
                    int rr = refl(rm, HH) * WW + refl(cm, WW);
                    contrib += (int)sb2(p[rr], pcv, g[rr], gcv);
                }
                int rp2 = r + dr, cp = c + dc;
                if ((unsigned)rp2 >= HH || (unsigned)cp >= WW) {
                    int rr = refl(rp2, HH) * WW + refl(cp, WW);
                    contrib -= (int)sb2(p[rr], pcv, g[rr], gcv);
                }
            }
        }
    }

    // ---------------- exact integer reduction + last-block finalize ----------------
    contrib = __reduce_add_sync(0xffffffffu, contrib);
    if ((tid & 31) == 0) wsum[tid >> 5] = contrib;
    __syncthreads();

    if (tid == 0) {
        int s = 0;
        #pragma unroll
        for (int w = 0; w < 8; ++w) s += wsum[w];
        atomicAdd(&g_acc, (unsigned)s);
        __threadfence();
        unsigned t = atomicAdd(&g_cnt, 1u);
        if (t == TOTAL_BLOCKS - 1) {
            __threadfence();
            unsigned total = atomicExch(&g_acc, 0u);   // read + reset for next replay
            out[0] = (float)((double)total / NELEM);
            g_cnt = 0;
        }
    }
}

extern "C" void kernel_launch(void* const* d_in, const int* in_sizes, int n_in,
                              void* d_out, int out_size)
{
    const float* pred = (const float*)d_in[0];
    const float* gt   = (const float*)d_in[1];
    float* out        = (float*)d_out;

    dim3 grid(WW / TW, HH / TH2 + 1, NIMG);   // (4, 17, 24): y==16 -> strip blocks
    census_kernel<<<grid, 256>>>(pred, gt, out);
}